// round 11
// baseline (speedup 1.0000x reference)
#include <cuda_runtime.h>
#include <cuda_bf16.h>

#define BATCH 128
#define NANCH 8732
#define NCLS  21
#define KTOP  200
#define CONF_T 0.01f
#define NMS_T  0.45f

// ---------------- scratch (device globals; no allocations allowed) ----------
__device__ float4 g_boxes[BATCH * NANCH];                       // ~17.9 MB
__device__ float  g_probs[(size_t)BATCH * 20 * NANCH];          // ~89.4 MB
__device__ float  g_sc[BATCH * 20 * KTOP];                      // kept scores
__device__ float4 g_sb[BATCH * 20 * KTOP];                      // kept boxes

// ---------------- kernel 1: decode + softmax ---------------------------------
__global__ void prep_kernel(const float* __restrict__ loc,
                            const float* __restrict__ conf,
                            const float* __restrict__ dbox) {
    __shared__ float sc[128 * NCLS];
    int b   = blockIdx.y;
    int n0  = blockIdx.x * 128;
    int tid = threadIdx.x;              // 128 threads
    int nrows = NANCH - n0; if (nrows > 128) nrows = 128;

    const float* cp = conf + ((size_t)b * NANCH + n0) * NCLS;
    for (int i = tid; i < nrows * NCLS; i += 128) sc[i] = cp[i];
    __syncthreads();

    if (tid < nrows) {
        int n = n0 + tid;
        const float* x = &sc[tid * NCLS];
        float m = x[0];
#pragma unroll
        for (int c = 1; c < NCLS; c++) m = fmaxf(m, x[c]);
        float e[NCLS];
        float s = 0.f;
#pragma unroll
        for (int c = 0; c < NCLS; c++) { e[c] = expf(x[c] - m); s += e[c]; }

        // decode box
        float4 l = reinterpret_cast<const float4*>(loc)[(size_t)b * NANCH + n];
        float4 d = reinterpret_cast<const float4*>(dbox)[n];
        float cx = d.x + l.x * 0.1f * d.z;
        float cy = d.y + l.y * 0.1f * d.w;
        float w  = d.z * expf(l.z * 0.2f);
        float h  = d.w * expf(l.w * 0.2f);
        float x1 = cx - w * 0.5f;
        float y1 = cy - h * 0.5f;
        float x2 = x1 + w;
        float y2 = y1 + h;
        x1 = fminf(fmaxf(x1, 0.f), 1.f);
        y1 = fminf(fmaxf(y1, 0.f), 1.f);
        x2 = fminf(fmaxf(x2, 0.f), 1.f);
        y2 = fminf(fmaxf(y2, 0.f), 1.f);
        g_boxes[(size_t)b * NANCH + n] = make_float4(x1, y1, x2, y2);

        // class-major probs (skip background class 0); coalesced per-c row
#pragma unroll
        for (int c = 1; c < NCLS; c++)
            g_probs[((size_t)b * 20 + (c - 1)) * NANCH + n] = e[c] / s;
    }
}

// ---------------- shared helpers ---------------------------------------------
__device__ __forceinline__ unsigned warp_suffix_incl(unsigned x) {
    unsigned lane = threadIdx.x & 31;
#pragma unroll
    for (int d = 1; d < 32; d <<= 1) {
        unsigned t = __shfl_down_sync(0xffffffffu, x, d);
        if (lane + d < 32) x += t;
    }
    return x;   // sum of x over lanes [lane..31]
}

// exclusive suffix over 256 threads: sum of x over threads with tid' > tid
__device__ __forceinline__ unsigned block_excl_suffix_256(unsigned x, unsigned* s_warp) {
    int lane = threadIdx.x & 31, wid = threadIdx.x >> 5;
    unsigned inc = warp_suffix_incl(x);
    if (lane == 0) s_warp[wid] = inc;
    __syncthreads();
    unsigned above = 0;
#pragma unroll
    for (int w = 0; w < 8; w++) if (w > wid) above += s_warp[w];
    return (inc - x) + above;
}

// bitonic sort of 256 u64 keys, descending; one element per thread (blockDim=256).
// sub-warp stages use shfl; cross-warp stages use the provided 256-slot scratch.
__device__ __forceinline__ unsigned long long bitonic256_desc(
        unsigned long long v, unsigned long long* sh) {
    int tid = threadIdx.x;
#pragma unroll
    for (int kk = 2; kk <= 256; kk <<= 1) {
        for (int j = kk >> 1; j > 0; j >>= 1) {
            unsigned long long w;
            if (j >= 32) {
                __syncthreads();
                sh[tid] = v;
                __syncthreads();
                w = sh[tid ^ j];
            } else {
                w = __shfl_xor_sync(0xffffffffu, v, j);
            }
            bool keepMax = ((tid & j) == 0) == ((tid & kk) == 0);
            if (keepMax ? (w > v) : (w < v)) v = w;
        }
    }
    return v;
}

// ---------------- kernel 2: per-(batch,class) top-200 + greedy NMS -----------
// All valid scores s in (0.01, 1] => bit31=0, bits[30:26]=01111; only bits[25:0]
// vary. Round 0: 16-bin histogram of bits[25:22] held in REGISTER-PACKED byte
// counters (no per-element shared atomics). Round 1: 256-bin atomic histogram
// of bits[21:14] over elements inside the selected 16-bin bucket only. The
// loose subbin-start pivot + full sort-256 yields the exact stable top-200
// whenever keys >= pivot number <= 256; rare deeper refines otherwise.
__global__ __launch_bounds__(256) void nms_kernel() {
    __shared__ unsigned hist[256];
    __shared__ unsigned long long cand[256];
    __shared__ float4 sbox[KTOP];
    __shared__ float  sarea[KTOP];
    __shared__ unsigned char salive[KTOP];
    __shared__ unsigned s_warp[8];
    __shared__ int selBin, selKk, sd0, skk1;
    __shared__ unsigned selCnt, s_total, s_cnt;

    int c    = blockIdx.x;               // 0..19 -> class c+1
    int b    = blockIdx.y;
    int tid  = threadIdx.x;              // 256 threads
    int lane = tid & 31;
    const float* __restrict__ row = g_probs + ((size_t)b * 20 + c) * NANCH;

    hist[tid] = 0;
    __syncthreads();

    // ---- round 0: register-packed 16-bin histogram of bits[25:22] ----
    // 8-bit fields; max 35 elements/thread < 255 so no overflow.
    unsigned long long rc0 = 0ull, rc1 = 0ull;
    for (int n = tid; n < NANCH; n += 256) {
        float s = row[n];
        if (s > CONF_T) {
            unsigned bin = (__float_as_uint(s) >> 22) & 15u;
            if (bin < 8u) rc0 += 1ull << (bin * 8u);
            else          rc1 += 1ull << ((bin - 8u) * 8u);
        }
    }
    {   // expand, warp-reduce, one atomic per (warp, bin): 128 atomics total
#pragma unroll
        for (int j = 0; j < 16; j++) {
            unsigned v = (j < 8) ? (unsigned)((rc0 >> (j * 8)) & 255ull)
                                 : (unsigned)((rc1 >> ((j - 8) * 8)) & 255ull);
#pragma unroll
            for (int d = 16; d > 0; d >>= 1) v += __shfl_down_sync(0xffffffffu, v, d);
            if (lane == 0 && v) atomicAdd(&hist[j], v);
        }
    }
    __syncthreads();

    if (tid == 0) {   // 16-bin suffix selection: trivial serial
        unsigned tot = 0;
        for (int j = 0; j < 16; j++) tot += hist[j];
        s_total = tot;
        unsigned above = 0; int d = 15;
        for (; d > 0; d--) {
            if (above + hist[d] >= (unsigned)KTOP) break;
            above += hist[d];
        }
        sd0 = d; skk1 = KTOP - (int)above;   // rank of the 200th within bin d
    }
    __syncthreads();

    unsigned pivot;
    if (s_total <= (unsigned)KTOP) {
        pivot = 1u;                          // take every thresholded key
    } else {
        int d0 = sd0, kk1 = skk1;
        unsigned above0 = (unsigned)(KTOP - kk1);
        // ---- round 1: bits[21:14] among keys in 16-bin bucket d0 only ----
        hist[tid] = 0;
        __syncthreads();
        for (int n = tid; n < NANCH; n += 256) {
            float s = row[n];
            if (s > CONF_T) {
                unsigned k = __float_as_uint(s);
                if (((k >> 22) & 15u) == (unsigned)d0)
                    atomicAdd(&hist[(k >> 14) & 255u], 1u);
            }
        }
        __syncthreads();
        {
            unsigned h = hist[tid];
            unsigned E = block_excl_suffix_256(h, s_warp);
            if (h + E >= (unsigned)kk1 && E < (unsigned)kk1) {
                selBin = tid; selKk = kk1 - (int)E; selCnt = above0 + E + h;
            }
        }
        __syncthreads();
        int d1 = selBin, kk2 = selKk;
        if (selCnt <= 256u) {
            // common: keys >= subbin start number selCnt (<=256); sort is exact
            pivot = (15u << 26) | ((unsigned)d0 << 22) | ((unsigned)d1 << 14);
        } else {
            // rare: refine bits[13:6] within prefix (d0,d1)
            unsigned above1 = (unsigned)(KTOP - kk2);
            unsigned pref12 = ((unsigned)d0 << 8) | (unsigned)d1;   // bits[25:14]
            hist[tid] = 0;
            __syncthreads();
            for (int n = tid; n < NANCH; n += 256) {
                float s = row[n];
                if (s > CONF_T) {
                    unsigned k = __float_as_uint(s);
                    if (((k >> 14) & 0xFFFu) == pref12)
                        atomicAdd(&hist[(k >> 6) & 255u], 1u);
                }
            }
            __syncthreads();
            {
                unsigned h = hist[tid];
                unsigned E = block_excl_suffix_256(h, s_warp);
                if (h + E >= (unsigned)kk2 && E < (unsigned)kk2) {
                    selBin = tid; selKk = kk2 - (int)E; selCnt = above1 + E + h;
                }
            }
            __syncthreads();
            int d2 = selBin, kk3 = selKk;
            if (selCnt <= 256u) {
                pivot = (15u << 26) | ((unsigned)d0 << 22) | ((unsigned)d1 << 14)
                      | ((unsigned)d2 << 6);
            } else {
                // rarest: exact last 6 bits within prefix (d0,d1,d2)
                unsigned pref20 = (pref12 << 8) | (unsigned)d2;     // bits[25:6]
                if (tid < 64) hist[tid] = 0;
                __syncthreads();
                for (int n = tid; n < NANCH; n += 256) {
                    float s = row[n];
                    if (s > CONF_T) {
                        unsigned k = __float_as_uint(s);
                        if (((k >> 6) & 0xFFFFFu) == pref20)
                            atomicAdd(&hist[k & 63u], 1u);
                    }
                }
                __syncthreads();
                {
                    unsigned h = (tid < 64) ? hist[tid] : 0u;
                    unsigned E = block_excl_suffix_256(h, s_warp);
                    if (tid < 64 && h + E >= (unsigned)kk3 && E < (unsigned)kk3)
                        selBin = tid;
                }
                __syncthreads();
                pivot = (15u << 26) | ((unsigned)d0 << 22) | ((unsigned)d1 << 14)
                      | ((unsigned)d2 << 6) | (unsigned)selBin;
            }
        }
    }

    if (tid == 0) s_cnt = 0;
    __syncthreads();

    // collect candidates (>= pivot, > CONF_T); 64-bit key = (scorebits, ~index)
    // -> stable descending order identical to jax.lax.top_k
    for (int n = tid; n < NANCH; n += 256) {
        float s = row[n];
        if (s > CONF_T) {
            unsigned k = __float_as_uint(s);
            if (k >= pivot) {
                unsigned p = atomicAdd(&s_cnt, 1u);
                if (p < 256u) cand[p] = ((unsigned long long)k << 32) | (unsigned)(~n);
            }
        }
    }
    __syncthreads();
    unsigned mcnt = s_cnt < 256u ? s_cnt : 256u;
    unsigned long long v = (tid < (int)mcnt) ? cand[tid] : 0ull;
    v = bitonic256_desc(v, cand);
    __syncthreads();              // all scratch reads done before overwrite
    cand[tid] = v;
    __syncthreads();

    // ---- NMS state: own candidate in registers, broadcast state in shared ----
    bool   myAlive = false;
    float4 myBox   = make_float4(0.f, 0.f, 0.f, 0.f);
    float  myArea  = 0.f;
    if (tid < KTOP) {
        unsigned long long vv = cand[tid];
        if (vv) {
            unsigned n = ~(unsigned)(vv & 0xFFFFFFFFu);
            myBox  = g_boxes[(size_t)b * NANCH + n];
            myArea = (myBox.z - myBox.x) * (myBox.w - myBox.y);
            myAlive = true;
        }
        sbox[tid]   = myBox;
        sarea[tid]  = myArea;
        salive[tid] = myAlive ? 1 : 0;
    }
    __syncthreads();

    // greedy NMS: alive[i] is final by step i, so final alive == keep
    for (int i = 0; i < KTOP; i++) {
        if (salive[i]) {                          // uniform read
            if (tid > i && myAlive) {
                float4 bi = sbox[i];
                float xx1 = fmaxf(myBox.x, bi.x), yy1 = fmaxf(myBox.y, bi.y);
                float xx2 = fminf(myBox.z, bi.z), yy2 = fminf(myBox.w, bi.w);
                float inter = fmaxf(xx2 - xx1, 0.f) * fmaxf(yy2 - yy1, 0.f);
                float iou = inter / (myArea + sarea[i] - inter);
                if (!(iou <= NMS_T)) { myAlive = false; salive[tid] = 0; }  // NaN -> suppress
            }
        }
        __syncthreads();
    }

    if (tid < KTOP) {
        int o = (b * 20 + c) * KTOP + tid;
        g_sc[o] = myAlive ? __uint_as_float((unsigned)(cand[tid] >> 32)) : 0.f;
        g_sb[o] = myAlive ? myBox : make_float4(0.f, 0.f, 0.f, 0.f);
    }
}

// ---------------- kernel 3: global top-200 + per-class compaction ------------
__global__ __launch_bounds__(256) void final_kernel(float* __restrict__ out) {
    __shared__ unsigned hist[1024];
    __shared__ unsigned long long cand[256];
    __shared__ unsigned s_warp[8];
    __shared__ int selBin, selKk;
    __shared__ unsigned s_total, s_cnt;

    int b   = blockIdx.x;
    int tid = threadIdx.x;              // 256 threads
    const float* __restrict__ sc = g_sc + b * 4000;

    for (int i = tid; i < 1024; i += 256) hist[i] = 0;
    __syncthreads();
    for (int n = tid; n < 4000; n += 256) {
        float s = sc[n];                // kept scores are 0 or > 0.01
        if (s > 0.f) atomicAdd(&hist[(__float_as_uint(s) >> 16) & 1023u], 1u);
    }
    __syncthreads();
    {
        unsigned h0 = hist[4*tid], h1 = hist[4*tid+1], h2 = hist[4*tid+2], h3 = hist[4*tid+3];
        unsigned s3 = h3, s2 = h2 + s3, s1 = h1 + s2, s0 = h0 + s1;
        unsigned E = block_excl_suffix_256(s0, s_warp);
        if (tid == 0) s_total = s0 + E;
        unsigned f0 = s0+E, f1 = s1+E, f2 = s2+E, f3 = s3+E, f4 = E;
        if (f0 >= KTOP && f1 < KTOP) { selBin = 4*tid+0; selKk = KTOP - (int)f1; }
        if (f1 >= KTOP && f2 < KTOP) { selBin = 4*tid+1; selKk = KTOP - (int)f2; }
        if (f2 >= KTOP && f3 < KTOP) { selBin = 4*tid+2; selKk = KTOP - (int)f3; }
        if (f3 >= KTOP && f4 < KTOP) { selBin = 4*tid+3; selKk = KTOP - (int)f4; }
    }
    __syncthreads();

    unsigned pivot = 1u;
    if (s_total > KTOP) {
        int d0 = selBin, kk1 = selKk;
        hist[tid] = 0;
        __syncthreads();
        for (int n = tid; n < 4000; n += 256) {
            float s = sc[n];
            if (s > 0.f) {
                unsigned k = __float_as_uint(s);
                if (((k >> 16) & 1023u) == (unsigned)d0)
                    atomicAdd(&hist[(k >> 8) & 255u], 1u);
            }
        }
        __syncthreads();
        {
            unsigned h = hist[tid];
            unsigned E = block_excl_suffix_256(h, s_warp);
            if (h + E >= (unsigned)kk1 && E < (unsigned)kk1) { selBin = tid; selKk = kk1 - (int)E; }
        }
        __syncthreads();
        int d1 = selBin, kk2 = selKk;
        unsigned pref = ((unsigned)d0 << 8) | (unsigned)d1;
        hist[tid] = 0;
        __syncthreads();
        for (int n = tid; n < 4000; n += 256) {
            float s = sc[n];
            if (s > 0.f) {
                unsigned k = __float_as_uint(s);
                if (((k >> 8) & 0x3FFFFu) == pref)
                    atomicAdd(&hist[k & 255u], 1u);
            }
        }
        __syncthreads();
        {
            unsigned h = hist[tid];
            unsigned E = block_excl_suffix_256(h, s_warp);
            if (h + E >= (unsigned)kk2 && E < (unsigned)kk2) { selBin = tid; }
        }
        __syncthreads();
        pivot = (15u << 26) | ((unsigned)d0 << 16) | ((unsigned)d1 << 8) | (unsigned)selBin;
    }

    if (tid == 0) s_cnt = 0;
    __syncthreads();
    for (int n = tid; n < 4000; n += 256) {
        float s = sc[n];
        if (s > 0.f) {
            unsigned k = __float_as_uint(s);
            if (k >= pivot) {
                unsigned p = atomicAdd(&s_cnt, 1u);
                if (p < 256u) cand[p] = ((unsigned long long)k << 32) | (unsigned)(~n);
            }
        }
    }
    __syncthreads();
    unsigned mcnt = s_cnt < 256u ? s_cnt : 256u;
    unsigned long long v = (tid < (int)mcnt) ? cand[tid] : 0ull;
    v = bitonic256_desc(v, cand);
    __syncthreads();
    cand[tid] = v;
    __syncthreads();

    // zero the whole batch output (poisoned by harness), then compact
    float* o = out + (size_t)b * NCLS * KTOP * 5;
    for (int i = tid; i < NCLS * KTOP * 5; i += 256) o[i] = 0.f;
    __syncthreads();

    if (tid < 20) {
        int cnt = 0;
        for (int k = 0; k < KTOP; k++) {            // global top-200 only
            unsigned long long vv = cand[k];
            if (!vv) break;                          // zeros sort last
            unsigned idx = ~(unsigned)(vv & 0xFFFFFFFFu);
            if ((int)(idx / KTOP) == tid) {          // class tid+1
                float s = __uint_as_float((unsigned)(vv >> 32));
                float4 bx = g_sb[b * 4000 + idx];
                float* dst = o + ((size_t)(tid + 1) * KTOP + cnt) * 5;
                dst[0] = s;
                dst[1] = bx.x; dst[2] = bx.y; dst[3] = bx.z; dst[4] = bx.w;
                cnt++;
            }
        }
    }
}

// ---------------- launch ------------------------------------------------------
extern "C" void kernel_launch(void* const* d_in, const int* in_sizes, int n_in,
                              void* d_out, int out_size) {
    const float* loc  = (const float*)d_in[0];   // [128, 8732, 4]
    const float* conf = (const float*)d_in[1];   // [128, 8732, 21]
    const float* dbox = (const float*)d_in[2];   // [8732, 4]
    float* out = (float*)d_out;                  // [128, 21, 200, 5]

    dim3 g1((NANCH + 127) / 128, BATCH);
    prep_kernel<<<g1, 128>>>(loc, conf, dbox);

    dim3 g2(20, BATCH);
    nms_kernel<<<g2, 256>>>();

    final_kernel<<<BATCH, 256>>>(out);
}